// round 8
// baseline (speedup 1.0000x reference)
#include <cuda_runtime.h>
#include <cuda_bf16.h>
#include <stdint.h>
#include <math.h>

// Problem constants
#define PB 2
#define PS 2048
#define PE 1024
#define PH 16
#define PD 64
#define PBS (PB * PS)   // 4096 rows

#define QSCALE (0.125f * 1.44269504088896f)   // 1/sqrt(64) * log2(e)

// ---------------------------------------------------------------------------
// Scratch (__device__ globals; no allocation allowed)
// ---------------------------------------------------------------------------
__device__ __nv_bfloat16 g_xh [(size_t)PBS * PE];
__device__ __nv_bfloat16 g_xl [(size_t)PBS * PE];
__device__ __nv_bfloat16 g_Qh [(size_t)PBS * PE];
__device__ __nv_bfloat16 g_Ql [(size_t)PBS * PE];
__device__ __nv_bfloat16 g_Kh [(size_t)PBS * PE];
__device__ __nv_bfloat16 g_Kl [(size_t)PBS * PE];
__device__ __nv_bfloat16 g_Vh [(size_t)PBS * PE];
__device__ __nv_bfloat16 g_Vl [(size_t)PBS * PE];
__device__ __nv_bfloat16 g_aoh[(size_t)PBS * PE];
__device__ __nv_bfloat16 g_aol[(size_t)PBS * PE];

// Transposed weight splits: Wt[n][k] = W[k][n], bf16 hi/lo
__device__ __nv_bfloat16 g_Wth[4][(size_t)PE * PE];
__device__ __nv_bfloat16 g_Wtl[4][(size_t)PE * PE];

// ---------------------------------------------------------------------------
// PTX helpers (sm_80-level ISA only; plain compute_103 target safe)
// ---------------------------------------------------------------------------
__device__ __forceinline__ uint32_t smem_u32(const void* p) {
    return (uint32_t)__cvta_generic_to_shared(p);
}

#define CP_ASYNC16(dst, src) \
    asm volatile("cp.async.cg.shared.global [%0], [%1], 16;" :: "r"(dst), "l"(src))
#define CP_COMMIT() asm volatile("cp.async.commit_group;")
#define CP_WAIT(N)  asm volatile("cp.async.wait_group %0;" :: "n"(N))

#define LDMATRIX_X4(R0, R1, R2, R3, addr) \
    asm volatile("ldmatrix.sync.aligned.m8n8.x4.shared.b16 {%0,%1,%2,%3}, [%4];" \
                 : "=r"(R0), "=r"(R1), "=r"(R2), "=r"(R3) : "r"(addr))

#define LDMATRIX_X4_T(R0, R1, R2, R3, addr) \
    asm volatile("ldmatrix.sync.aligned.m8n8.x4.trans.shared.b16 {%0,%1,%2,%3}, [%4];" \
                 : "=r"(R0), "=r"(R1), "=r"(R2), "=r"(R3) : "r"(addr))

#define MMA16816(D, A0, A1, A2, A3, B0, B1) \
    asm volatile("mma.sync.aligned.m16n8k16.row.col.f32.bf16.bf16.f32 " \
                 "{%0,%1,%2,%3}, {%4,%5,%6,%7}, {%8,%9}, {%0,%1,%2,%3};" \
                 : "+f"((D)[0]), "+f"((D)[1]), "+f"((D)[2]), "+f"((D)[3]) \
                 : "r"(A0), "r"(A1), "r"(A2), "r"(A3), "r"(B0), "r"(B1))

__device__ __forceinline__ float ex2(float x) {
    float y;
    asm("ex2.approx.ftz.f32 %0, %1;" : "=f"(y) : "f"(x));
    return y;
}

// split (a,b) into packed bf16x2 hi and lo words (a = low half); 1-cvt fast path
__device__ __forceinline__ void split2(float a, float b, uint32_t& hi, uint32_t& lo) {
    __nv_bfloat162 h2 = __floats2bfloat162_rn(a, b);
    uint32_t h = *reinterpret_cast<uint32_t*>(&h2);
    float fa = __uint_as_float(h << 16);
    float fb = __uint_as_float(h & 0xFFFF0000u);
    __nv_bfloat162 l2 = __floats2bfloat162_rn(a - fa, b - fb);
    hi = h;
    lo = *reinterpret_cast<uint32_t*>(&l2);
}

// ---------------------------------------------------------------------------
// GEMM body: C[4096,1024] = (A @ Wt^T + bias) * scale
// Precision: per k-chunk, acc += Ah*Bh + Ah*Bl + Al*Bh (fp32 accum).
// CTA tile 128x128, k-chunk 32 (32 iterations), 8 warps (warp tile 32x64).
// SMEM: hi|lo interleaved 128-B rows, xor-swizzled; 3-stage cp.async ring.
// MMA order: pass-major within pi -> same-accumulator distance 4 (was 2).
// ---------------------------------------------------------------------------
#define GBM 128
#define GBN 128
#define NKI 32                 // 1024 / 32
#define SROW 128               // bytes per smem row (32 hi bf16 | 32 lo bf16)
#define A_ST (128 * SROW)      // 16384 per array per stage
#define SSTG (2 * A_ST)        // 32768 per stage (A + B)
#define GEMM_SMEM_BYTES (3 * SSTG)   // 98304

__device__ __forceinline__ uint32_t sw_off(uint32_t row, uint32_t chunk) {
    return row * SROW + ((chunk ^ (row & 7u)) << 4);
}

__device__ __forceinline__ void gemm_body(
    const __nv_bfloat16* __restrict__ Ah, const __nv_bfloat16* __restrict__ Al,
    const __nv_bfloat16* __restrict__ Bh, const __nv_bfloat16* __restrict__ Bl,
    const float* __restrict__ bias, float scale,
    float* __restrict__ outF,
    __nv_bfloat16* __restrict__ outH, __nv_bfloat16* __restrict__ outL,
    char* smem)
{
    const int tid  = threadIdx.x;
    const int wid  = tid >> 5;
    const int lane = tid & 31;
    const int wm   = wid & 3;
    const int wn   = wid >> 2;
    const int row0 = blockIdx.y * GBM;
    const int col0 = blockIdx.x * GBN;

    const uint32_t sbase = smem_u32(smem);

    const uint32_t lc = tid & 7;
    const uint32_t lr = tid >> 3;
    const bool isHi = lc < 4;
    const int  koff = (int)((lc & 3) << 3);

    float acc[2][8][4];
#pragma unroll
    for (int i = 0; i < 2; ++i)
#pragma unroll
        for (int j = 0; j < 8; ++j)
#pragma unroll
            for (int v = 0; v < 4; ++v) acc[i][j][v] = 0.f;

    auto issue_load = [&](int s) {
        const uint32_t st = (uint32_t)(s % 3) * SSTG;
        const int k0 = s << 5;
        const __nv_bfloat16* Asrc = isHi ? Ah : Al;
        const __nv_bfloat16* Bsrc = isHi ? Bh : Bl;
#pragma unroll
        for (int rr = 0; rr < 128; rr += 32) {
            const uint32_t r = lr + rr;
            CP_ASYNC16(sbase + st + sw_off(r, lc),
                       Asrc + (size_t)(row0 + r) * PE + k0 + koff);
            CP_ASYNC16(sbase + st + A_ST + sw_off(r, lc),
                       Bsrc + (size_t)(col0 + r) * PE + k0 + koff);
        }
    };

    issue_load(0); CP_COMMIT();
    issue_load(1); CP_COMMIT();

#pragma unroll 1
    for (int s = 0; s < NKI; ++s) {
        if (s < NKI - 1) CP_WAIT(1);
        else             CP_WAIT(0);
        __syncthreads();
        if (s + 2 < NKI) { issue_load(s + 2); CP_COMMIT(); }

        const uint32_t aB = sbase + (uint32_t)(s % 3) * SSTG;
        const uint32_t bB = aB + A_ST;
#pragma unroll
        for (int ks = 0; ks < 2; ++ks) {
            uint32_t ah[2][4], al[2][4];
#pragma unroll
            for (int mi = 0; mi < 2; ++mi) {
                uint32_t arow = (uint32_t)(wm * 32 + mi * 16 + (lane & 15));
                uint32_t hchunk = (uint32_t)(ks * 2 + (lane >> 4));
                LDMATRIX_X4(ah[mi][0], ah[mi][1], ah[mi][2], ah[mi][3],
                            aB + sw_off(arow, hchunk));
                LDMATRIX_X4(al[mi][0], al[mi][1], al[mi][2], al[mi][3],
                            aB + sw_off(arow, hchunk + 4));
            }
#pragma unroll
            for (int pi = 0; pi < 4; ++pi) {
                uint32_t brow = (uint32_t)(wn * 64 + pi * 16 +
                                           ((lane >> 4) << 3) + (lane & 7));
                uint32_t hchunk = (uint32_t)(ks * 2 + ((lane >> 3) & 1));
                uint32_t bh0, bh1, bh2, bh3, bl0, bl1, bl2, bl3;
                LDMATRIX_X4(bh0, bh1, bh2, bh3, bB + sw_off(brow, hchunk));
                LDMATRIX_X4(bl0, bl1, bl2, bl3, bB + sw_off(brow, hchunk + 4));
                // pass-major: same-acc distance 4
#pragma unroll
                for (int mi = 0; mi < 2; ++mi) {
                    MMA16816(acc[mi][2 * pi],     ah[mi][0], ah[mi][1], ah[mi][2], ah[mi][3], bh0, bh1);
                    MMA16816(acc[mi][2 * pi + 1], ah[mi][0], ah[mi][1], ah[mi][2], ah[mi][3], bh2, bh3);
                }
#pragma unroll
                for (int mi = 0; mi < 2; ++mi) {
                    MMA16816(acc[mi][2 * pi],     ah[mi][0], ah[mi][1], ah[mi][2], ah[mi][3], bl0, bl1);
                    MMA16816(acc[mi][2 * pi + 1], ah[mi][0], ah[mi][1], ah[mi][2], ah[mi][3], bl2, bl3);
                }
#pragma unroll
                for (int mi = 0; mi < 2; ++mi) {
                    MMA16816(acc[mi][2 * pi],     al[mi][0], al[mi][1], al[mi][2], al[mi][3], bh0, bh1);
                    MMA16816(acc[mi][2 * pi + 1], al[mi][0], al[mi][1], al[mi][2], al[mi][3], bh2, bh3);
                }
            }
        }
    }

    // Epilogue
    const int tr  = lane >> 2;
    const int tc2 = (lane & 3) * 2;
#pragma unroll
    for (int mi = 0; mi < 2; ++mi) {
#pragma unroll
        for (int ni = 0; ni < 8; ++ni) {
            int col = col0 + wn * 64 + ni * 8 + tc2;
            float2 bi = *reinterpret_cast<const float2*>(bias + col);
            int r1 = row0 + wm * 32 + mi * 16 + tr;
            float v0 = (acc[mi][ni][0] + bi.x) * scale;
            float v1 = (acc[mi][ni][1] + bi.y) * scale;
            float v2 = (acc[mi][ni][2] + bi.x) * scale;
            float v3 = (acc[mi][ni][3] + bi.y) * scale;
            if (outF) {
                *reinterpret_cast<float2*>(&outF[(size_t)r1 * PE + col]) =
                    make_float2(v0, v1);
                *reinterpret_cast<float2*>(&outF[(size_t)(r1 + 8) * PE + col]) =
                    make_float2(v2, v3);
            } else {
                uint32_t h01, l01, h23, l23;
                split2(v0, v1, h01, l01);
                split2(v2, v3, h23, l23);
                *reinterpret_cast<uint32_t*>(outH + (size_t)r1 * PE + col) = h01;
                *reinterpret_cast<uint32_t*>(outL + (size_t)r1 * PE + col) = l01;
                *reinterpret_cast<uint32_t*>(outH + (size_t)(r1 + 8) * PE + col) = h23;
                *reinterpret_cast<uint32_t*>(outL + (size_t)(r1 + 8) * PE + col) = l23;
            }
        }
    }
}

// Fused Q/K/V projection: blockIdx.z selects weight/bias/output/scale.
__global__ __launch_bounds__(256, 2) void gemm_qkv_kernel(
    const __nv_bfloat16* __restrict__ xh, const __nv_bfloat16* __restrict__ xl,
    const __nv_bfloat16* __restrict__ Wth, const __nv_bfloat16* __restrict__ Wtl,
    const float* __restrict__ bq, const float* __restrict__ bk,
    const float* __restrict__ bv,
    __nv_bfloat16* __restrict__ Qh, __nv_bfloat16* __restrict__ Ql,
    __nv_bfloat16* __restrict__ Kh, __nv_bfloat16* __restrict__ Kl,
    __nv_bfloat16* __restrict__ Vh, __nv_bfloat16* __restrict__ Vl)
{
    extern __shared__ char smem[];
    const int z = blockIdx.z;
    const size_t WSZ = (size_t)PE * PE;
    const float* bias = (z == 0) ? bq : (z == 1) ? bk : bv;
    __nv_bfloat16* oh = (z == 0) ? Qh : (z == 1) ? Kh : Vh;
    __nv_bfloat16* ol = (z == 0) ? Ql : (z == 1) ? Kl : Vl;
    const float scale = (z == 0) ? QSCALE : 1.f;
    gemm_body(xh, xl, Wth + z * WSZ, Wtl + z * WSZ, bias, scale,
              nullptr, oh, ol, smem);
}

// O-projection (fp32 output)
__global__ __launch_bounds__(256, 2) void gemm_o_kernel(
    const __nv_bfloat16* __restrict__ aoh, const __nv_bfloat16* __restrict__ aol,
    const __nv_bfloat16* __restrict__ Bh, const __nv_bfloat16* __restrict__ Bl,
    const float* __restrict__ bias, float* __restrict__ outF)
{
    extern __shared__ char smem[];
    gemm_body(aoh, aol, Bh, Bl, bias, 1.f, outF, nullptr, nullptr, smem);
}

// ---------------------------------------------------------------------------
// fp32 -> (hi, lo) bf16 split (x only), 4 elems/thread vectorized
// ---------------------------------------------------------------------------
__global__ __launch_bounds__(256) void split_kernel(
    const float* __restrict__ in, __nv_bfloat16* __restrict__ hi,
    __nv_bfloat16* __restrict__ lo, int n4)
{
    int i = blockIdx.x * 256 + threadIdx.x;
    if (i < n4) {
        float4 v = reinterpret_cast<const float4*>(in)[i];
        uint32_t h01, l01, h23, l23;
        split2(v.x, v.y, h01, l01);
        split2(v.z, v.w, h23, l23);
        reinterpret_cast<uint2*>(hi)[i] = make_uint2(h01, h23);
        reinterpret_cast<uint2*>(lo)[i] = make_uint2(l01, l23);
    }
}

// W[k][n] fp32 -> Wt[n][k] bf16 hi/lo; z selects which of 4 weights
__global__ __launch_bounds__(256) void transpose_split_kernel(
    const float* __restrict__ W0, const float* __restrict__ W1,
    const float* __restrict__ W2, const float* __restrict__ W3,
    __nv_bfloat16* __restrict__ Th, __nv_bfloat16* __restrict__ Tl)
{
    __shared__ float t[32][33];
    const int z = blockIdx.z;
    const float* W = (z == 0) ? W0 : (z == 1) ? W1 : (z == 2) ? W2 : W3;
    const size_t WSZ = (size_t)PE * PE;
    __nv_bfloat16* Thz = Th + z * WSZ;
    __nv_bfloat16* Tlz = Tl + z * WSZ;
    const int n0 = blockIdx.x * 32;
    const int k0 = blockIdx.y * 32;
    const int tx = threadIdx.x & 31;
    const int ty = threadIdx.x >> 5;
#pragma unroll
    for (int i = 0; i < 32; i += 8)
        t[ty + i][tx] = W[(size_t)(k0 + ty + i) * PE + n0 + tx];
    __syncthreads();
#pragma unroll
    for (int i = 0; i < 32; i += 8) {
        float v = t[tx][ty + i];
        __nv_bfloat16 h = __float2bfloat16(v);
        size_t idx = (size_t)(n0 + ty + i) * PE + k0 + tx;
        Thz[idx] = h;
        Tlz[idx] = __float2bfloat16(v - __bfloat162float(h));
    }
}

// ---------------------------------------------------------------------------
// Flash attention with mma.sync bf16 + hi/lo splitting.
// QK and PV products issued as 3 pass-major sweeps each:
// same-accumulator MMA distance 8 (was 2); fragments re-loaded per pass.
// ---------------------------------------------------------------------------
#define LDT 72                  // smem row stride in bf16 (144 B)
#define TSZ (64 * LDT)
#define STILE(buf, arr) (((buf) * 4 + (arr)) * TSZ)
#define ATTN_SMEM_BYTES (8 * TSZ * 2)   // 73728

__global__ __launch_bounds__(128, 3) void attn_mma_kernel(
    const __nv_bfloat16* __restrict__ Qh_g, const __nv_bfloat16* __restrict__ Ql_g,
    const __nv_bfloat16* __restrict__ Kh_g, const __nv_bfloat16* __restrict__ Kl_g,
    const __nv_bfloat16* __restrict__ Vh_g, const __nv_bfloat16* __restrict__ Vl_g,
    __nv_bfloat16* __restrict__ AOh, __nv_bfloat16* __restrict__ AOl)
{
    extern __shared__ __nv_bfloat16 smemb[];
    const uint32_t sb = smem_u32(smemb);

    const int tid  = threadIdx.x;
    const int lane = tid & 31;
    const int wm   = tid >> 5;
    const int qb   = gridDim.x - 1 - blockIdx.x;
    const int q0   = qb * 64;
    const int bh   = blockIdx.y;
    const int b    = bh >> 4;
    const int h    = bh & 15;
    const size_t base = (size_t)b * PS * PE + (size_t)h * PD;

    auto ld_tile = [&](const __nv_bfloat16* g, uint32_t soff, int row0g) {
#pragma unroll
        for (int it = 0; it < 4; ++it) {
            int i = tid + it * 128;
            int r = i >> 3, c = i & 7;
            uint32_t dst = sb + (soff + r * LDT + c * 8) * 2;
            const void* src = g + base + (size_t)(row0g + r) * PE + c * 8;
            CP_ASYNC16(dst, src);
        }
    };

    // ---- Q staging (overlaid on ring buf0) ----
    ld_tile(Qh_g, STILE(0, 0), q0);
    ld_tile(Ql_g, STILE(0, 1), q0);
    CP_COMMIT();
    CP_WAIT(0);
    __syncthreads();

    uint32_t qfh[4][4], qfl[4][4];
    {
        uint32_t qoff = ((uint32_t)(wm * 16 + (lane & 15)) * LDT + (lane >> 4) * 8) * 2;
#pragma unroll
        for (int ks = 0; ks < 4; ++ks) {
            LDMATRIX_X4(qfh[ks][0], qfh[ks][1], qfh[ks][2], qfh[ks][3],
                        sb + (STILE(0, 0) * 2) + qoff + ks * 32);
            LDMATRIX_X4(qfl[ks][0], qfl[ks][1], qfl[ks][2], qfl[ks][3],
                        sb + (STILE(0, 1) * 2) + qoff + ks * 32);
        }
    }
    __syncthreads();   // all warps done reading Q before KV overwrites buf0

    // ---- KV tile 0 into ring buf0 ----
    ld_tile(Kh_g, STILE(0, 0), 0);
    ld_tile(Kl_g, STILE(0, 1), 0);
    ld_tile(Vh_g, STILE(0, 2), 0);
    ld_tile(Vl_g, STILE(0, 3), 0);
    CP_COMMIT();

    float O[8][4];
#pragma unroll
    for (int g = 0; g < 8; ++g)
#pragma unroll
        for (int j = 0; j < 4; ++j) O[g][j] = 0.f;
    float m0 = -1e30f, m1 = -1e30f, sl0 = 0.f, sl1 = 0.f;

    const uint32_t klo = ((((lane >> 4) << 3) + (lane & 7)) * LDT + ((lane >> 3) & 1) * 8) * 2;
    const uint32_t vlo = ((lane & 15) * LDT + (lane >> 4) * 8) * 2;
    const int ntiles = qb + 1;

#pragma unroll 1
    for (int t = 0; t < ntiles; ++t) {
        const int buf = t & 1;
        if (t + 1 < ntiles) {
            const int kv1 = (t + 1) * 64;
            ld_tile(Kh_g, STILE(buf ^ 1, 0), kv1);
            ld_tile(Kl_g, STILE(buf ^ 1, 1), kv1);
            ld_tile(Vh_g, STILE(buf ^ 1, 2), kv1);
            ld_tile(Vl_g, STILE(buf ^ 1, 3), kv1);
            CP_COMMIT();
            CP_WAIT(1);
        } else {
            CP_WAIT(0);
        }
        __syncthreads();

        const uint32_t kHb = sb + STILE(buf, 0) * 2;
        const uint32_t kLb = sb + STILE(buf, 1) * 2;
        const uint32_t vHb = sb + STILE(buf, 2) * 2;
        const uint32_t vLb = sb + STILE(buf, 3) * 2;

        float S[8][4];
#pragma unroll
        for (int g = 0; g < 8; ++g)
#pragma unroll
            for (int j = 0; j < 4; ++j) S[g][j] = 0.f;

        // ---- S = QK^T: 3 pass-major sweeps (same-acc distance 8) ----
#define QK_PASS(QF, KB)                                                        \
        _Pragma("unroll")                                                      \
        for (int ks = 0; ks < 4; ++ks) {                                       \
            _Pragma("unroll")                                                  \
            for (int ni = 0; ni < 4; ++ni) {                                   \
                uint32_t off = klo + (uint32_t)(ni * 16 * LDT + ks * 16) * 2;  \
                uint32_t f0, f1, f2, f3;                                       \
                LDMATRIX_X4(f0, f1, f2, f3, (KB) + off);                       \
                MMA16816(S[2 * ni],     QF[ks][0], QF[ks][1], QF[ks][2], QF[ks][3], f0, f1); \
                MMA16816(S[2 * ni + 1], QF[ks][0], QF[ks][1], QF[ks][2], QF[ks][3], f2, f3); \
            }                                                                  \
        }
        QK_PASS(qfh, kHb)
        QK_PASS(qfh, kLb)
        QK_PASS(qfl, kHb)
#undef QK_PASS

        if (t == ntiles - 1) {
            const int kv0 = t * 64;
            const int row0g = q0 + wm * 16 + (lane >> 2);
#pragma unroll
            for (int g = 0; g < 8; ++g) {
                int colg = kv0 + 8 * g + ((lane & 3) << 1);
                if (colg > row0g)         S[g][0] = -1e30f;
                if (colg + 1 > row0g)     S[g][1] = -1e30f;
                if (colg > row0g + 8)     S[g][2] = -1e30f;
                if (colg + 1 > row0g + 8) S[g][3] = -1e30f;
            }
        }

        float mt0 = -1e30f, mt1 = -1e30f;
#pragma unroll
        for (int g = 0; g < 8; ++g) {
            mt0 = fmaxf(mt0, fmaxf(S[g][0], S[g][1]));
            mt1 = fmaxf(mt1, fmaxf(S[g][2], S[g][3]));
        }
        mt0 = fmaxf(mt0, __shfl_xor_sync(0xffffffffu, mt0, 1));
        mt0 = fmaxf(mt0, __shfl_xor_sync(0xffffffffu, mt0, 2));
        mt1 = fmaxf(mt1, __shfl_xor_sync(0xffffffffu, mt1, 1));
        mt1 = fmaxf(mt1, __shfl_xor_sync(0xffffffffu, mt1, 2));
        float mn0 = fmaxf(m0, mt0), mn1 = fmaxf(m1, mt1);
        float c0 = ex2(m0 - mn0), c1 = ex2(m1 - mn1);
        m0 = mn0; m1 = mn1;
        float rs0 = 0.f, rs1 = 0.f;
#pragma unroll
        for (int g = 0; g < 8; ++g) {
            S[g][0] = ex2(S[g][0] - mn0); rs0 += S[g][0];
            S[g][1] = ex2(S[g][1] - mn0); rs0 += S[g][1];
            S[g][2] = ex2(S[g][2] - mn1); rs1 += S[g][2];
            S[g][3] = ex2(S[g][3] - mn1); rs1 += S[g][3];
        }
        rs0 += __shfl_xor_sync(0xffffffffu, rs0, 1);
        rs0 += __shfl_xor_sync(0xffffffffu, rs0, 2);
        rs1 += __shfl_xor_sync(0xffffffffu, rs1, 1);
        rs1 += __shfl_xor_sync(0xffffffffu, rs1, 2);
        sl0 = sl0 * c0 + rs0;
        sl1 = sl1 * c1 + rs1;
#pragma unroll
        for (int g = 0; g < 8; ++g) {
            O[g][0] *= c0; O[g][1] *= c0;
            O[g][2] *= c1; O[g][3] *= c1;
        }

        // ---- split ALL P fragments (S dies here), then 3 PV sweeps ----
        uint32_t ph[4][4], pl[4][4];
#pragma unroll
        for (int ks = 0; ks < 4; ++ks) {
            split2(S[2 * ks][0],     S[2 * ks][1],     ph[ks][0], pl[ks][0]);
            split2(S[2 * ks][2],     S[2 * ks][3],     ph[ks][1], pl[ks][1]);
            split2(S[2 * ks + 1][0], S[2 * ks + 1][1], ph[ks][2], pl[ks][2]);
            split2(S[2 * ks + 1][2], S[2 * ks + 1][3], ph[ks][3], pl[ks][3]);
        }

#define PV_PASS(PF, VB)                                                        \
        _Pragma("unroll")                                                      \
        for (int ks = 0; ks < 4; ++ks) {                                       \
            _Pragma("unroll")                                                  \
            for (int ni = 0; ni < 4; ++ni) {                                   \
                uint32_t off = vlo + (uint32_t)(ks * 16 * LDT + ni * 16) * 2;  \
                uint32_t f0, f1, f2, f3;                                       \
                LDMATRIX_X4_T(f0, f1, f2, f3, (VB) + off);                     \
                MMA16816(O[2 * ni],     PF[ks][0], PF[ks][1], PF[ks][2], PF[ks][3], f0, f1); \
                MMA16816(O[2 * ni + 1], PF[ks][0], PF[ks][1], PF[ks][2], PF[ks][3], f2, f3); \
            }                                                                  \
        }
        PV_PASS(ph, vHb)
        PV_PASS(ph, vLb)
        PV_PASS(pl, vHb)
#undef PV_PASS

        __syncthreads();
    }

    const float inv0 = 1.f / sl0;
    const float inv1 = 1.f / sl1;
    const int r0g = q0 + wm * 16 + (lane >> 2);
#pragma unroll
    for (int g = 0; g < 8; ++g) {
        int colg = 8 * g + ((lane & 3) << 1);
        size_t i0 = base + (size_t)r0g * PE + colg;
        size_t i1 = base + (size_t)(r0g + 8) * PE + colg;
        uint32_t h01, l01, h23, l23;
        split2(O[g][0] * inv0, O[g][1] * inv0, h01, l01);
        split2(O[g][2] * inv1, O[g][3] * inv1, h23, l23);
        *reinterpret_cast<uint32_t*>(AOh + i0) = h01;
        *reinterpret_cast<uint32_t*>(AOl + i0) = l01;
        *reinterpret_cast<uint32_t*>(AOh + i1) = h23;
        *reinterpret_cast<uint32_t*>(AOl + i1) = l23;
    }
}

// ---------------------------------------------------------------------------
extern "C" void kernel_launch(void* const* d_in, const int* in_sizes, int n_in,
                              void* d_out, int out_size)
{
    const float* x  = (const float*)d_in[0];
    const float* Wq = (const float*)d_in[1];
    const float* bq = (const float*)d_in[2];
    const float* Wk = (const float*)d_in[3];
    const float* bk = (const float*)d_in[4];
    const float* Wv = (const float*)d_in[5];
    const float* bv = (const float*)d_in[6];
    const float* Wo = (const float*)d_in[7];
    const float* bo = (const float*)d_in[8];
    float* out = (float*)d_out;

    __nv_bfloat16 *xh, *xl, *Qh, *Ql, *Kh, *Kl, *Vh, *Vl, *aoh, *aol, *Wth, *Wtl;
    cudaGetSymbolAddress((void**)&xh,  g_xh);
    cudaGetSymbolAddress((void**)&xl,  g_xl);
    cudaGetSymbolAddress((void**)&Qh,  g_Qh);
    cudaGetSymbolAddress((void**)&Ql,  g_Ql);
    cudaGetSymbolAddress((void**)&Kh,  g_Kh);
    cudaGetSymbolAddress((void**)&Kl,  g_Kl);
    cudaGetSymbolAddress((void**)&Vh,  g_Vh);
    cudaGetSymbolAddress((void**)&Vl,  g_Vl);
    cudaGetSymbolAddress((void**)&aoh, g_aoh);
    cudaGetSymbolAddress((void**)&aol, g_aol);
    cudaGetSymbolAddress((void**)&Wth, g_Wth);
    cudaGetSymbolAddress((void**)&Wtl, g_Wtl);

    cudaFuncSetAttribute(attn_mma_kernel,
                         cudaFuncAttributeMaxDynamicSharedMemorySize,
                         ATTN_SMEM_BYTES);
    cudaFuncSetAttribute(gemm_qkv_kernel,
                         cudaFuncAttributeMaxDynamicSharedMemorySize,
                         GEMM_SMEM_BYTES);
    cudaFuncSetAttribute(gemm_o_kernel,
                         cudaFuncAttributeMaxDynamicSharedMemorySize,
                         GEMM_SMEM_BYTES);

    const size_t WSZ = (size_t)PE * PE;
    const int nX4 = PBS * PE / 4;

    split_kernel<<<(nX4 + 255) / 256, 256>>>(x, xh, xl, nX4);
    transpose_split_kernel<<<dim3(PE / 32, PE / 32, 4), 256>>>(
        Wq, Wk, Wv, Wo, Wth, Wtl);

    gemm_qkv_kernel<<<dim3(PE / GBN, PBS / GBM, 3), 256, GEMM_SMEM_BYTES>>>(
        xh, xl, Wth, Wtl, bq, bk, bv, Qh, Ql, Kh, Kl, Vh, Vl);

    attn_mma_kernel<<<dim3(PS / 64, PB * PH), 128, ATTN_SMEM_BYTES>>>(
        Qh, Ql, Kh, Kl, Vh, Vl, aoh, aol);

    gemm_o_kernel<<<dim3(PE / GBN, PBS / GBM), 256, GEMM_SMEM_BYTES>>>(
        aoh, aol, Wth + 3 * WSZ, Wtl + 3 * WSZ, bo, out);
}

// round 9
// speedup vs baseline: 1.0332x; 1.0332x over previous
#include <cuda_runtime.h>
#include <cuda_bf16.h>
#include <stdint.h>
#include <math.h>

// Problem constants
#define PB 2
#define PS 2048
#define PE 1024
#define PH 16
#define PD 64
#define PBS (PB * PS)   // 4096 rows

#define QSCALE (0.125f * 1.44269504088896f)   // 1/sqrt(64) * log2(e)

// ---------------------------------------------------------------------------
// Scratch (__device__ globals; no allocation allowed)
// ---------------------------------------------------------------------------
__device__ __nv_bfloat16 g_xh [(size_t)PBS * PE];
__device__ __nv_bfloat16 g_xl [(size_t)PBS * PE];
__device__ __nv_bfloat16 g_Qh [(size_t)PBS * PE];
__device__ __nv_bfloat16 g_Ql [(size_t)PBS * PE];
__device__ __nv_bfloat16 g_Kh [(size_t)PBS * PE];
__device__ __nv_bfloat16 g_Kl [(size_t)PBS * PE];
__device__ __nv_bfloat16 g_Vh [(size_t)PBS * PE];
__device__ __nv_bfloat16 g_Vl [(size_t)PBS * PE];
__device__ __nv_bfloat16 g_aoh[(size_t)PBS * PE];
__device__ __nv_bfloat16 g_aol[(size_t)PBS * PE];

// Transposed weight splits: Wt[n][k] = W[k][n], bf16 hi/lo
__device__ __nv_bfloat16 g_Wth[4][(size_t)PE * PE];
__device__ __nv_bfloat16 g_Wtl[4][(size_t)PE * PE];

// ---------------------------------------------------------------------------
// PTX helpers (sm_80-level ISA only; plain compute_103 target safe)
// ---------------------------------------------------------------------------
__device__ __forceinline__ uint32_t smem_u32(const void* p) {
    return (uint32_t)__cvta_generic_to_shared(p);
}

#define CP_ASYNC16(dst, src) \
    asm volatile("cp.async.cg.shared.global [%0], [%1], 16;" :: "r"(dst), "l"(src))
#define CP_COMMIT() asm volatile("cp.async.commit_group;")
#define CP_WAIT(N)  asm volatile("cp.async.wait_group %0;" :: "n"(N))

#define LDMATRIX_X4(R0, R1, R2, R3, addr) \
    asm volatile("ldmatrix.sync.aligned.m8n8.x4.shared.b16 {%0,%1,%2,%3}, [%4];" \
                 : "=r"(R0), "=r"(R1), "=r"(R2), "=r"(R3) : "r"(addr))

#define LDMATRIX_X4_T(R0, R1, R2, R3, addr) \
    asm volatile("ldmatrix.sync.aligned.m8n8.x4.trans.shared.b16 {%0,%1,%2,%3}, [%4];" \
                 : "=r"(R0), "=r"(R1), "=r"(R2), "=r"(R3) : "r"(addr))

#define MMA16816(D, A0, A1, A2, A3, B0, B1) \
    asm volatile("mma.sync.aligned.m16n8k16.row.col.f32.bf16.bf16.f32 " \
                 "{%0,%1,%2,%3}, {%4,%5,%6,%7}, {%8,%9}, {%0,%1,%2,%3};" \
                 : "+f"((D)[0]), "+f"((D)[1]), "+f"((D)[2]), "+f"((D)[3]) \
                 : "r"(A0), "r"(A1), "r"(A2), "r"(A3), "r"(B0), "r"(B1))

__device__ __forceinline__ float ex2(float x) {
    float y;
    asm("ex2.approx.ftz.f32 %0, %1;" : "=f"(y) : "f"(x));
    return y;
}

// split (a,b) into packed bf16x2 hi and lo words (a = low half); 1-cvt fast path
__device__ __forceinline__ void split2(float a, float b, uint32_t& hi, uint32_t& lo) {
    __nv_bfloat162 h2 = __floats2bfloat162_rn(a, b);
    uint32_t h = *reinterpret_cast<uint32_t*>(&h2);
    float fa = __uint_as_float(h << 16);
    float fb = __uint_as_float(h & 0xFFFF0000u);
    __nv_bfloat162 l2 = __floats2bfloat162_rn(a - fa, b - fb);
    hi = h;
    lo = *reinterpret_cast<uint32_t*>(&l2);
}

// ---------------------------------------------------------------------------
// GEMM body: C[4096,1024] = (A @ Wt^T + bias) * scale
// Precision: per k-chunk, acc += Ah*Bh + Ah*Bl + Al*Bh (fp32 accum).
// CTA tile 128x128, k-chunk 32 (32 iterations), 8 warps (warp tile 32x64).
// SMEM: hi|lo interleaved 128-B rows, xor-swizzled; 3-stage cp.async ring.
// (unchanged from R8 — the pass-major GEMM ordering helped there)
// ---------------------------------------------------------------------------
#define GBM 128
#define GBN 128
#define NKI 32                 // 1024 / 32
#define SROW 128               // bytes per smem row (32 hi bf16 | 32 lo bf16)
#define A_ST (128 * SROW)      // 16384 per array per stage
#define SSTG (2 * A_ST)        // 32768 per stage (A + B)
#define GEMM_SMEM_BYTES (3 * SSTG)   // 98304

__device__ __forceinline__ uint32_t sw_off(uint32_t row, uint32_t chunk) {
    return row * SROW + ((chunk ^ (row & 7u)) << 4);
}

__device__ __forceinline__ void gemm_body(
    const __nv_bfloat16* __restrict__ Ah, const __nv_bfloat16* __restrict__ Al,
    const __nv_bfloat16* __restrict__ Bh, const __nv_bfloat16* __restrict__ Bl,
    const float* __restrict__ bias, float scale,
    float* __restrict__ outF,
    __nv_bfloat16* __restrict__ outH, __nv_bfloat16* __restrict__ outL,
    char* smem)
{
    const int tid  = threadIdx.x;
    const int wid  = tid >> 5;
    const int lane = tid & 31;
    const int wm   = wid & 3;
    const int wn   = wid >> 2;
    const int row0 = blockIdx.y * GBM;
    const int col0 = blockIdx.x * GBN;

    const uint32_t sbase = smem_u32(smem);

    const uint32_t lc = tid & 7;
    const uint32_t lr = tid >> 3;
    const bool isHi = lc < 4;
    const int  koff = (int)((lc & 3) << 3);

    float acc[2][8][4];
#pragma unroll
    for (int i = 0; i < 2; ++i)
#pragma unroll
        for (int j = 0; j < 8; ++j)
#pragma unroll
            for (int v = 0; v < 4; ++v) acc[i][j][v] = 0.f;

    auto issue_load = [&](int s) {
        const uint32_t st = (uint32_t)(s % 3) * SSTG;
        const int k0 = s << 5;
        const __nv_bfloat16* Asrc = isHi ? Ah : Al;
        const __nv_bfloat16* Bsrc = isHi ? Bh : Bl;
#pragma unroll
        for (int rr = 0; rr < 128; rr += 32) {
            const uint32_t r = lr + rr;
            CP_ASYNC16(sbase + st + sw_off(r, lc),
                       Asrc + (size_t)(row0 + r) * PE + k0 + koff);
            CP_ASYNC16(sbase + st + A_ST + sw_off(r, lc),
                       Bsrc + (size_t)(col0 + r) * PE + k0 + koff);
        }
    };

    issue_load(0); CP_COMMIT();
    issue_load(1); CP_COMMIT();

#pragma unroll 1
    for (int s = 0; s < NKI; ++s) {
        if (s < NKI - 1) CP_WAIT(1);
        else             CP_WAIT(0);
        __syncthreads();
        if (s + 2 < NKI) { issue_load(s + 2); CP_COMMIT(); }

        const uint32_t aB = sbase + (uint32_t)(s % 3) * SSTG;
        const uint32_t bB = aB + A_ST;
#pragma unroll
        for (int ks = 0; ks < 2; ++ks) {
            uint32_t ah[2][4], al[2][4];
#pragma unroll
            for (int mi = 0; mi < 2; ++mi) {
                uint32_t arow = (uint32_t)(wm * 32 + mi * 16 + (lane & 15));
                uint32_t hchunk = (uint32_t)(ks * 2 + (lane >> 4));
                LDMATRIX_X4(ah[mi][0], ah[mi][1], ah[mi][2], ah[mi][3],
                            aB + sw_off(arow, hchunk));
                LDMATRIX_X4(al[mi][0], al[mi][1], al[mi][2], al[mi][3],
                            aB + sw_off(arow, hchunk + 4));
            }
#pragma unroll
            for (int pi = 0; pi < 4; ++pi) {
                uint32_t brow = (uint32_t)(wn * 64 + pi * 16 +
                                           ((lane >> 4) << 3) + (lane & 7));
                uint32_t hchunk = (uint32_t)(ks * 2 + ((lane >> 3) & 1));
                uint32_t bh0, bh1, bh2, bh3, bl0, bl1, bl2, bl3;
                LDMATRIX_X4(bh0, bh1, bh2, bh3, bB + sw_off(brow, hchunk));
                LDMATRIX_X4(bl0, bl1, bl2, bl3, bB + sw_off(brow, hchunk + 4));
#pragma unroll
                for (int mi = 0; mi < 2; ++mi) {
                    MMA16816(acc[mi][2 * pi],     ah[mi][0], ah[mi][1], ah[mi][2], ah[mi][3], bh0, bh1);
                    MMA16816(acc[mi][2 * pi + 1], ah[mi][0], ah[mi][1], ah[mi][2], ah[mi][3], bh2, bh3);
                }
#pragma unroll
                for (int mi = 0; mi < 2; ++mi) {
                    MMA16816(acc[mi][2 * pi],     ah[mi][0], ah[mi][1], ah[mi][2], ah[mi][3], bl0, bl1);
                    MMA16816(acc[mi][2 * pi + 1], ah[mi][0], ah[mi][1], ah[mi][2], ah[mi][3], bl2, bl3);
                }
#pragma unroll
                for (int mi = 0; mi < 2; ++mi) {
                    MMA16816(acc[mi][2 * pi],     al[mi][0], al[mi][1], al[mi][2], al[mi][3], bh0, bh1);
                    MMA16816(acc[mi][2 * pi + 1], al[mi][0], al[mi][1], al[mi][2], al[mi][3], bh2, bh3);
                }
            }
        }
    }

    // Epilogue
    const int tr  = lane >> 2;
    const int tc2 = (lane & 3) * 2;
#pragma unroll
    for (int mi = 0; mi < 2; ++mi) {
#pragma unroll
        for (int ni = 0; ni < 8; ++ni) {
            int col = col0 + wn * 64 + ni * 8 + tc2;
            float2 bi = *reinterpret_cast<const float2*>(bias + col);
            int r1 = row0 + wm * 32 + mi * 16 + tr;
            float v0 = (acc[mi][ni][0] + bi.x) * scale;
            float v1 = (acc[mi][ni][1] + bi.y) * scale;
            float v2 = (acc[mi][ni][2] + bi.x) * scale;
            float v3 = (acc[mi][ni][3] + bi.y) * scale;
            if (outF) {
                *reinterpret_cast<float2*>(&outF[(size_t)r1 * PE + col]) =
                    make_float2(v0, v1);
                *reinterpret_cast<float2*>(&outF[(size_t)(r1 + 8) * PE + col]) =
                    make_float2(v2, v3);
            } else {
                uint32_t h01, l01, h23, l23;
                split2(v0, v1, h01, l01);
                split2(v2, v3, h23, l23);
                *reinterpret_cast<uint32_t*>(outH + (size_t)r1 * PE + col) = h01;
                *reinterpret_cast<uint32_t*>(outL + (size_t)r1 * PE + col) = l01;
                *reinterpret_cast<uint32_t*>(outH + (size_t)(r1 + 8) * PE + col) = h23;
                *reinterpret_cast<uint32_t*>(outL + (size_t)(r1 + 8) * PE + col) = l23;
            }
        }
    }
}

// Fused Q/K/V projection: blockIdx.z selects weight/bias/output/scale.
__global__ __launch_bounds__(256, 2) void gemm_qkv_kernel(
    const __nv_bfloat16* __restrict__ xh, const __nv_bfloat16* __restrict__ xl,
    const __nv_bfloat16* __restrict__ Wth, const __nv_bfloat16* __restrict__ Wtl,
    const float* __restrict__ bq, const float* __restrict__ bk,
    const float* __restrict__ bv,
    __nv_bfloat16* __restrict__ Qh, __nv_bfloat16* __restrict__ Ql,
    __nv_bfloat16* __restrict__ Kh, __nv_bfloat16* __restrict__ Kl,
    __nv_bfloat16* __restrict__ Vh, __nv_bfloat16* __restrict__ Vl)
{
    extern __shared__ char smem[];
    const int z = blockIdx.z;
    const size_t WSZ = (size_t)PE * PE;
    const float* bias = (z == 0) ? bq : (z == 1) ? bk : bv;
    __nv_bfloat16* oh = (z == 0) ? Qh : (z == 1) ? Kh : Vh;
    __nv_bfloat16* ol = (z == 0) ? Ql : (z == 1) ? Kl : Vl;
    const float scale = (z == 0) ? QSCALE : 1.f;
    gemm_body(xh, xl, Wth + z * WSZ, Wtl + z * WSZ, bias, scale,
              nullptr, oh, ol, smem);
}

// O-projection (fp32 output)
__global__ __launch_bounds__(256, 2) void gemm_o_kernel(
    const __nv_bfloat16* __restrict__ aoh, const __nv_bfloat16* __restrict__ aol,
    const __nv_bfloat16* __restrict__ Bh, const __nv_bfloat16* __restrict__ Bl,
    const float* __restrict__ bias, float* __restrict__ outF)
{
    extern __shared__ char smem[];
    gemm_body(aoh, aol, Bh, Bl, bias, 1.f, outF, nullptr, nullptr, smem);
}

// ---------------------------------------------------------------------------
// fp32 -> (hi, lo) bf16 split (x only), 4 elems/thread vectorized
// ---------------------------------------------------------------------------
__global__ __launch_bounds__(256) void split_kernel(
    const float* __restrict__ in, __nv_bfloat16* __restrict__ hi,
    __nv_bfloat16* __restrict__ lo, int n4)
{
    int i = blockIdx.x * 256 + threadIdx.x;
    if (i < n4) {
        float4 v = reinterpret_cast<const float4*>(in)[i];
        uint32_t h01, l01, h23, l23;
        split2(v.x, v.y, h01, l01);
        split2(v.z, v.w, h23, l23);
        reinterpret_cast<uint2*>(hi)[i] = make_uint2(h01, h23);
        reinterpret_cast<uint2*>(lo)[i] = make_uint2(l01, l23);
    }
}

// W[k][n] fp32 -> Wt[n][k] bf16 hi/lo; z selects which of 4 weights
__global__ __launch_bounds__(256) void transpose_split_kernel(
    const float* __restrict__ W0, const float* __restrict__ W1,
    const float* __restrict__ W2, const float* __restrict__ W3,
    __nv_bfloat16* __restrict__ Th, __nv_bfloat16* __restrict__ Tl)
{
    __shared__ float t[32][33];
    const int z = blockIdx.z;
    const float* W = (z == 0) ? W0 : (z == 1) ? W1 : (z == 2) ? W2 : W3;
    const size_t WSZ = (size_t)PE * PE;
    __nv_bfloat16* Thz = Th + z * WSZ;
    __nv_bfloat16* Tlz = Tl + z * WSZ;
    const int n0 = blockIdx.x * 32;
    const int k0 = blockIdx.y * 32;
    const int tx = threadIdx.x & 31;
    const int ty = threadIdx.x >> 5;
#pragma unroll
    for (int i = 0; i < 32; i += 8)
        t[ty + i][tx] = W[(size_t)(k0 + ty + i) * PE + n0 + tx];
    __syncthreads();
#pragma unroll
    for (int i = 0; i < 32; i += 8) {
        float v = t[tx][ty + i];
        __nv_bfloat16 h = __float2bfloat16(v);
        size_t idx = (size_t)(n0 + ty + i) * PE + k0 + tx;
        Thz[idx] = h;
        Tlz[idx] = __float2bfloat16(v - __bfloat162float(h));
    }
}

// ---------------------------------------------------------------------------
// Flash attention with mma.sync bf16 + hi/lo splitting.
// R7 interleaved MMA ordering (proven fastest) + SINGLE barrier per KV tile:
// top __syncthreads guarantees all warps finished iter t-1 reads of buf^1,
// so prefetch(t+1) into buf^1 issued AFTER the barrier is safe; the bottom
// barrier is deleted (ring depth 2, same smem, 3 CTAs/SM).
// ---------------------------------------------------------------------------
#define LDT 72                  // smem row stride in bf16 (144 B)
#define TSZ (64 * LDT)
#define STILE(buf, arr) (((buf) * 4 + (arr)) * TSZ)
#define ATTN_SMEM_BYTES (8 * TSZ * 2)   // 73728

__global__ __launch_bounds__(128, 3) void attn_mma_kernel(
    const __nv_bfloat16* __restrict__ Qh_g, const __nv_bfloat16* __restrict__ Ql_g,
    const __nv_bfloat16* __restrict__ Kh_g, const __nv_bfloat16* __restrict__ Kl_g,
    const __nv_bfloat16* __restrict__ Vh_g, const __nv_bfloat16* __restrict__ Vl_g,
    __nv_bfloat16* __restrict__ AOh, __nv_bfloat16* __restrict__ AOl)
{
    extern __shared__ __nv_bfloat16 smemb[];
    const uint32_t sb = smem_u32(smemb);

    const int tid  = threadIdx.x;
    const int lane = tid & 31;
    const int wm   = tid >> 5;
    const int qb   = gridDim.x - 1 - blockIdx.x;
    const int q0   = qb * 64;
    const int bh   = blockIdx.y;
    const int b    = bh >> 4;
    const int h    = bh & 15;
    const size_t base = (size_t)b * PS * PE + (size_t)h * PD;

    auto ld_tile = [&](const __nv_bfloat16* g, uint32_t soff, int row0g) {
#pragma unroll
        for (int it = 0; it < 4; ++it) {
            int i = tid + it * 128;
            int r = i >> 3, c = i & 7;
            uint32_t dst = sb + (soff + r * LDT + c * 8) * 2;
            const void* src = g + base + (size_t)(row0g + r) * PE + c * 8;
            CP_ASYNC16(dst, src);
        }
    };

    // ---- Q staging (overlaid on ring buf0) ----
    ld_tile(Qh_g, STILE(0, 0), q0);
    ld_tile(Ql_g, STILE(0, 1), q0);
    CP_COMMIT();
    CP_WAIT(0);
    __syncthreads();

    uint32_t qfh[4][4], qfl[4][4];
    {
        uint32_t qoff = ((uint32_t)(wm * 16 + (lane & 15)) * LDT + (lane >> 4) * 8) * 2;
#pragma unroll
        for (int ks = 0; ks < 4; ++ks) {
            LDMATRIX_X4(qfh[ks][0], qfh[ks][1], qfh[ks][2], qfh[ks][3],
                        sb + (STILE(0, 0) * 2) + qoff + ks * 32);
            LDMATRIX_X4(qfl[ks][0], qfl[ks][1], qfl[ks][2], qfl[ks][3],
                        sb + (STILE(0, 1) * 2) + qoff + ks * 32);
        }
    }
    __syncthreads();   // all warps done reading Q before KV overwrites buf0

    // ---- KV tile 0 into ring buf0 ----
    ld_tile(Kh_g, STILE(0, 0), 0);
    ld_tile(Kl_g, STILE(0, 1), 0);
    ld_tile(Vh_g, STILE(0, 2), 0);
    ld_tile(Vl_g, STILE(0, 3), 0);
    CP_COMMIT();

    float O[8][4];
#pragma unroll
    for (int g = 0; g < 8; ++g)
#pragma unroll
        for (int j = 0; j < 4; ++j) O[g][j] = 0.f;
    float m0 = -1e30f, m1 = -1e30f, sl0 = 0.f, sl1 = 0.f;

    const uint32_t klo = ((((lane >> 4) << 3) + (lane & 7)) * LDT + ((lane >> 3) & 1) * 8) * 2;
    const uint32_t vlo = ((lane & 15) * LDT + (lane >> 4) * 8) * 2;
    const int ntiles = qb + 1;

#pragma unroll 1
    for (int t = 0; t < ntiles; ++t) {
        const int buf = t & 1;
        // ONE barrier per tile: all warps done reading buf^1 (iteration t-1)
        __syncthreads();
        if (t + 1 < ntiles) {
            const int kv1 = (t + 1) * 64;
            ld_tile(Kh_g, STILE(buf ^ 1, 0), kv1);
            ld_tile(Kl_g, STILE(buf ^ 1, 1), kv1);
            ld_tile(Vh_g, STILE(buf ^ 1, 2), kv1);
            ld_tile(Vl_g, STILE(buf ^ 1, 3), kv1);
            CP_COMMIT();
            CP_WAIT(1);   // load(t) complete
        } else {
            CP_WAIT(0);
        }

        const uint32_t kHb = sb + STILE(buf, 0) * 2;
        const uint32_t kLb = sb + STILE(buf, 1) * 2;
        const uint32_t vHb = sb + STILE(buf, 2) * 2;
        const uint32_t vLb = sb + STILE(buf, 3) * 2;

        float S[8][4];
#pragma unroll
        for (int g = 0; g < 8; ++g)
#pragma unroll
            for (int j = 0; j < 4; ++j) S[g][j] = 0.f;

        // ---- S = QK^T (R7 interleaved ordering) ----
#pragma unroll
        for (int ks = 0; ks < 4; ++ks) {
#pragma unroll
            for (int ni = 0; ni < 4; ++ni) {
                uint32_t off = klo + (uint32_t)(ni * 16 * LDT + ks * 16) * 2;
                uint32_t bh0, bh1, bh2, bh3, bl0, bl1, bl2, bl3;
                LDMATRIX_X4(bh0, bh1, bh2, bh3, kHb + off);
                LDMATRIX_X4(bl0, bl1, bl2, bl3, kLb + off);
                MMA16816(S[2 * ni],     qfh[ks][0], qfh[ks][1], qfh[ks][2], qfh[ks][3], bh0, bh1);
                MMA16816(S[2 * ni + 1], qfh[ks][0], qfh[ks][1], qfh[ks][2], qfh[ks][3], bh2, bh3);
                MMA16816(S[2 * ni],     qfh[ks][0], qfh[ks][1], qfh[ks][2], qfh[ks][3], bl0, bl1);
                MMA16816(S[2 * ni + 1], qfh[ks][0], qfh[ks][1], qfh[ks][2], qfh[ks][3], bl2, bl3);
                MMA16816(S[2 * ni],     qfl[ks][0], qfl[ks][1], qfl[ks][2], qfl[ks][3], bh0, bh1);
                MMA16816(S[2 * ni + 1], qfl[ks][0], qfl[ks][1], qfl[ks][2], qfl[ks][3], bh2, bh3);
            }
        }

        if (t == ntiles - 1) {
            const int kv0 = t * 64;
            const int row0g = q0 + wm * 16 + (lane >> 2);
#pragma unroll
            for (int g = 0; g < 8; ++g) {
                int colg = kv0 + 8 * g + ((lane & 3) << 1);
                if (colg > row0g)         S[g][0] = -1e30f;
                if (colg + 1 > row0g)     S[g][1] = -1e30f;
                if (colg > row0g + 8)     S[g][2] = -1e30f;
                if (colg + 1 > row0g + 8) S[g][3] = -1e30f;
            }
        }

        float mt0 = -1e30f, mt1 = -1e30f;
#pragma unroll
        for (int g = 0; g < 8; ++g) {
            mt0 = fmaxf(mt0, fmaxf(S[g][0], S[g][1]));
            mt1 = fmaxf(mt1, fmaxf(S[g][2], S[g][3]));
        }
        mt0 = fmaxf(mt0, __shfl_xor_sync(0xffffffffu, mt0, 1));
        mt0 = fmaxf(mt0, __shfl_xor_sync(0xffffffffu, mt0, 2));
        mt1 = fmaxf(mt1, __shfl_xor_sync(0xffffffffu, mt1, 1));
        mt1 = fmaxf(mt1, __shfl_xor_sync(0xffffffffu, mt1, 2));
        float mn0 = fmaxf(m0, mt0), mn1 = fmaxf(m1, mt1);
        float c0 = ex2(m0 - mn0), c1 = ex2(m1 - mn1);
        m0 = mn0; m1 = mn1;
        float rs0 = 0.f, rs1 = 0.f;
#pragma unroll
        for (int g = 0; g < 8; ++g) {
            S[g][0] = ex2(S[g][0] - mn0); rs0 += S[g][0];
            S[g][1] = ex2(S[g][1] - mn0); rs0 += S[g][1];
            S[g][2] = ex2(S[g][2] - mn1); rs1 += S[g][2];
            S[g][3] = ex2(S[g][3] - mn1); rs1 += S[g][3];
        }
        rs0 += __shfl_xor_sync(0xffffffffu, rs0, 1);
        rs0 += __shfl_xor_sync(0xffffffffu, rs0, 2);
        rs1 += __shfl_xor_sync(0xffffffffu, rs1, 1);
        rs1 += __shfl_xor_sync(0xffffffffu, rs1, 2);
        sl0 = sl0 * c0 + rs0;
        sl1 = sl1 * c1 + rs1;
#pragma unroll
        for (int g = 0; g < 8; ++g) {
            O[g][0] *= c0; O[g][1] *= c0;
            O[g][2] *= c1; O[g][3] *= c1;
        }

        // ---- O += P V (R7 interleaved ordering) ----
#pragma unroll
        for (int ks = 0; ks < 4; ++ks) {
            uint32_t pha[4], pla[4];
            split2(S[2 * ks][0],     S[2 * ks][1],     pha[0], pla[0]);
            split2(S[2 * ks][2],     S[2 * ks][3],     pha[1], pla[1]);
            split2(S[2 * ks + 1][0], S[2 * ks + 1][1], pha[2], pla[2]);
            split2(S[2 * ks + 1][2], S[2 * ks + 1][3], pha[3], pla[3]);
#pragma unroll
            for (int ni = 0; ni < 4; ++ni) {
                uint32_t off = vlo + (uint32_t)(ks * 16 * LDT + ni * 16) * 2;
                uint32_t vh0, vh1, vh2, vh3, vl0_, vl1_, vl2_, vl3_;
                LDMATRIX_X4_T(vh0, vh1, vh2, vh3, vHb + off);
                LDMATRIX_X4_T(vl0_, vl1_, vl2_, vl3_, vLb + off);
                MMA16816(O[2 * ni],     pha[0], pha[1], pha[2], pha[3], vh0, vh1);
                MMA16816(O[2 * ni + 1], pha[0], pha[1], pha[2], pha[3], vh2, vh3);
                MMA16816(O[2 * ni],     pha[0], pha[1], pha[2], pha[3], vl0_, vl1_);
                MMA16816(O[2 * ni + 1], pha[0], pha[1], pha[2], pha[3], vl2_, vl3_);
                MMA16816(O[2 * ni],     pla[0], pla[1], pla[2], pla[3], vh0, vh1);
                MMA16816(O[2 * ni + 1], pla[0], pla[1], pla[2], pla[3], vh2, vh3);
            }
        }
        // no bottom barrier: prefetch for the next tile is issued only after
        // the next iteration's top __syncthreads
    }

    const float inv0 = 1.f / sl0;
    const float inv1 = 1.f / sl1;
    const int r0g = q0 + wm * 16 + (lane >> 2);
#pragma unroll
    for (int g = 0; g < 8; ++g) {
        int colg = 8 * g + ((lane & 3) << 1);
        size_t i0 = base + (size_t)r0g * PE + colg;
        size_t i1 = base + (size_t)(r0g + 8) * PE + colg;
        uint32_t h01, l01, h23, l23;
        split2(O[g][0] * inv0, O[g][1] * inv0, h01, l01);
        split2(O[g][2] * inv1, O[g][3] * inv1, h23, l23);
        *reinterpret_cast<uint32_t*>(AOh + i0) = h01;
        *reinterpret_cast<uint32_t*>(AOl + i0) = l01;
        *reinterpret_cast<uint32_t*>(AOh + i1) = h23;
        *reinterpret_cast<uint32_t*>(AOl + i1) = l23;
    }
}

// ---------------------------------------------------------------------------
extern "C" void kernel_launch(void* const* d_in, const int* in_sizes, int n_in,
                              void* d_out, int out_size)
{
    const float* x  = (const float*)d_in[0];
    const float* Wq = (const float*)d_in[1];
    const float* bq = (const float*)d_in[2];
    const float* Wk = (const float*)d_in[3];
    const float* bk = (const float*)d_in[4];
    const float* Wv = (const float*)d_in[5];
    const float* bv = (const float*)d_in[6];
    const float* Wo = (const float*)d_in[7];
    const float* bo = (const float*)d_in[8];
    float* out = (float*)d_out;

    __nv_bfloat16 *xh, *xl, *Qh, *Ql, *Kh, *Kl, *Vh, *Vl, *aoh, *aol, *Wth, *Wtl;
    cudaGetSymbolAddress((void**)&xh,  g_xh);
    cudaGetSymbolAddress((void**)&xl,  g_xl);
    cudaGetSymbolAddress((void**)&Qh,  g_Qh);
    cudaGetSymbolAddress((void**)&Ql,  g_Ql);
    cudaGetSymbolAddress((void**)&Kh,  g_Kh);
    cudaGetSymbolAddress((void**)&Kl,  g_Kl);
    cudaGetSymbolAddress((void**)&Vh,  g_Vh);
    cudaGetSymbolAddress((void**)&Vl,  g_Vl);
    cudaGetSymbolAddress((void**)&aoh, g_aoh);
    cudaGetSymbolAddress((void**)&aol, g_aol);
    cudaGetSymbolAddress((void**)&Wth, g_Wth);
    cudaGetSymbolAddress((void**)&Wtl, g_Wtl);

    cudaFuncSetAttribute(attn_mma_kernel,
                         cudaFuncAttributeMaxDynamicSharedMemorySize,
                         ATTN_SMEM_BYTES);
    cudaFuncSetAttribute(gemm_qkv_kernel,
                         cudaFuncAttributeMaxDynamicSharedMemorySize,
                         GEMM_SMEM_BYTES);
    cudaFuncSetAttribute(gemm_o_kernel,
                         cudaFuncAttributeMaxDynamicSharedMemorySize,
                         GEMM_SMEM_BYTES);

    const size_t WSZ = (size_t)PE * PE;
    const int nX4 = PBS * PE / 4;

    split_kernel<<<(nX4 + 255) / 256, 256>>>(x, xh, xl, nX4);
    transpose_split_kernel<<<dim3(PE / 32, PE / 32, 4), 256>>>(
        Wq, Wk, Wv, Wo, Wth, Wtl);

    gemm_qkv_kernel<<<dim3(PE / GBN, PBS / GBM, 3), 256, GEMM_SMEM_BYTES>>>(
        xh, xl, Wth, Wtl, bq, bk, bv, Qh, Ql, Kh, Kl, Vh, Vl);

    attn_mma_kernel<<<dim3(PS / 64, PB * PH), 128, ATTN_SMEM_BYTES>>>(
        Qh, Ql, Kh, Kl, Vh, Vl, aoh, aol);

    gemm_o_kernel<<<dim3(PE / GBN, PBS / GBM), 256, GEMM_SMEM_BYTES>>>(
        aoh, aol, Wth + 3 * WSZ, Wtl + 3 * WSZ, bo, out);
}

// round 10
// speedup vs baseline: 1.0567x; 1.0227x over previous
#include <cuda_runtime.h>
#include <cuda_bf16.h>
#include <stdint.h>
#include <math.h>

// Problem constants
#define PB 2
#define PS 2048
#define PE 1024
#define PH 16
#define PD 64
#define PBS (PB * PS)   // 4096 rows

#define QSCALE (0.125f * 1.44269504088896f)   // 1/sqrt(64) * log2(e)

// ---------------------------------------------------------------------------
// Scratch (__device__ globals; no allocation allowed)
// ---------------------------------------------------------------------------
__device__ __nv_bfloat16 g_xh [(size_t)PBS * PE];
__device__ __nv_bfloat16 g_xl [(size_t)PBS * PE];
__device__ __nv_bfloat16 g_Qh [(size_t)PBS * PE];
__device__ __nv_bfloat16 g_Ql [(size_t)PBS * PE];
__device__ __nv_bfloat16 g_Kh [(size_t)PBS * PE];
__device__ __nv_bfloat16 g_Kl [(size_t)PBS * PE];
__device__ __nv_bfloat16 g_Vh [(size_t)PBS * PE];
__device__ __nv_bfloat16 g_Vl [(size_t)PBS * PE];
__device__ __nv_bfloat16 g_aoh[(size_t)PBS * PE];
__device__ __nv_bfloat16 g_aol[(size_t)PBS * PE];

// Transposed weight splits: Wt[n][k] = W[k][n], bf16 hi/lo
__device__ __nv_bfloat16 g_Wth[4][(size_t)PE * PE];
__device__ __nv_bfloat16 g_Wtl[4][(size_t)PE * PE];

// ---------------------------------------------------------------------------
// PTX helpers (sm_80/90 base ISA; plain compute_103 target safe)
// ---------------------------------------------------------------------------
__device__ __forceinline__ uint32_t smem_u32(const void* p) {
    return (uint32_t)__cvta_generic_to_shared(p);
}

#define CP_ASYNC16(dst, src) \
    asm volatile("cp.async.cg.shared.global [%0], [%1], 16;" :: "r"(dst), "l"(src))
#define CP_COMMIT() asm volatile("cp.async.commit_group;")
#define CP_WAIT(N)  asm volatile("cp.async.wait_group %0;" :: "n"(N))

#define MBAR_INIT(addr, cnt) \
    asm volatile("mbarrier.init.shared.b64 [%0], %1;" :: "r"(addr), "r"(cnt) : "memory")
#define MBAR_ARRIVE(addr) \
    asm volatile("mbarrier.arrive.shared.b64 _, [%0];" :: "r"(addr) : "memory")
#define CP_MBAR_ARRIVE(addr) \
    asm volatile("cp.async.mbarrier.arrive.noinc.shared.b64 [%0];" :: "r"(addr) : "memory")

#define MBAR_WAIT_PARITY(mbar_addr, phase_parity) do {                              \
    uint32_t _mbar = (uint32_t)(mbar_addr);                                         \
    uint32_t _parity = (uint32_t)(phase_parity);                                    \
    uint32_t _done;                                                                 \
    asm volatile(                                                                   \
        "{\n\t.reg .pred p;\n\t"                                                    \
        "mbarrier.try_wait.parity.acquire.cta.shared::cta.b64 p, [%1], %2;\n\t"     \
        "selp.b32 %0, 1, 0, p;\n\t}"                                                \
        : "=r"(_done) : "r"(_mbar), "r"(_parity) : "memory");                       \
    if (!_done) {                                                                   \
        asm volatile(                                                               \
            "{\n\t.reg .pred P1;\n\t"                                               \
            "WAIT_LOOP_%=:\n\t"                                                     \
            "mbarrier.try_wait.parity.acquire.cta.shared::cta.b64 P1, [%0], %1, 0x989680;\n\t" \
            "@P1 bra.uni WAIT_DONE_%=;\n\t"                                         \
            "bra.uni WAIT_LOOP_%=;\n\t"                                             \
            "WAIT_DONE_%=:\n\t}"                                                    \
            :: "r"(_mbar), "r"(_parity) : "memory");                                \
    }                                                                               \
} while (0)

#define LDMATRIX_X4(R0, R1, R2, R3, addr) \
    asm volatile("ldmatrix.sync.aligned.m8n8.x4.shared.b16 {%0,%1,%2,%3}, [%4];" \
                 : "=r"(R0), "=r"(R1), "=r"(R2), "=r"(R3) : "r"(addr))

#define LDMATRIX_X4_T(R0, R1, R2, R3, addr) \
    asm volatile("ldmatrix.sync.aligned.m8n8.x4.trans.shared.b16 {%0,%1,%2,%3}, [%4];" \
                 : "=r"(R0), "=r"(R1), "=r"(R2), "=r"(R3) : "r"(addr))

#define MMA16816(D, A0, A1, A2, A3, B0, B1) \
    asm volatile("mma.sync.aligned.m16n8k16.row.col.f32.bf16.bf16.f32 " \
                 "{%0,%1,%2,%3}, {%4,%5,%6,%7}, {%8,%9}, {%0,%1,%2,%3};" \
                 : "+f"((D)[0]), "+f"((D)[1]), "+f"((D)[2]), "+f"((D)[3]) \
                 : "r"(A0), "r"(A1), "r"(A2), "r"(A3), "r"(B0), "r"(B1))

__device__ __forceinline__ float ex2(float x) {
    float y;
    asm("ex2.approx.ftz.f32 %0, %1;" : "=f"(y) : "f"(x));
    return y;
}

// split (a,b) into packed bf16x2 hi and lo words (a = low half); 1-cvt fast path
__device__ __forceinline__ void split2(float a, float b, uint32_t& hi, uint32_t& lo) {
    __nv_bfloat162 h2 = __floats2bfloat162_rn(a, b);
    uint32_t h = *reinterpret_cast<uint32_t*>(&h2);
    float fa = __uint_as_float(h << 16);
    float fb = __uint_as_float(h & 0xFFFF0000u);
    __nv_bfloat162 l2 = __floats2bfloat162_rn(a - fa, b - fb);
    hi = h;
    lo = *reinterpret_cast<uint32_t*>(&l2);
}

// ---------------------------------------------------------------------------
// GEMM body (unchanged from R9)
// ---------------------------------------------------------------------------
#define GBM 128
#define GBN 128
#define NKI 32                 // 1024 / 32
#define SROW 128               // bytes per smem row (32 hi bf16 | 32 lo bf16)
#define A_ST (128 * SROW)      // 16384 per array per stage
#define SSTG (2 * A_ST)        // 32768 per stage (A + B)
#define GEMM_SMEM_BYTES (3 * SSTG)   // 98304

__device__ __forceinline__ uint32_t sw_off(uint32_t row, uint32_t chunk) {
    return row * SROW + ((chunk ^ (row & 7u)) << 4);
}

__device__ __forceinline__ void gemm_body(
    const __nv_bfloat16* __restrict__ Ah, const __nv_bfloat16* __restrict__ Al,
    const __nv_bfloat16* __restrict__ Bh, const __nv_bfloat16* __restrict__ Bl,
    const float* __restrict__ bias, float scale,
    float* __restrict__ outF,
    __nv_bfloat16* __restrict__ outH, __nv_bfloat16* __restrict__ outL,
    char* smem)
{
    const int tid  = threadIdx.x;
    const int wid  = tid >> 5;
    const int lane = tid & 31;
    const int wm   = wid & 3;
    const int wn   = wid >> 2;
    const int row0 = blockIdx.y * GBM;
    const int col0 = blockIdx.x * GBN;

    const uint32_t sbase = smem_u32(smem);

    const uint32_t lc = tid & 7;
    const uint32_t lr = tid >> 3;
    const bool isHi = lc < 4;
    const int  koff = (int)((lc & 3) << 3);

    float acc[2][8][4];
#pragma unroll
    for (int i = 0; i < 2; ++i)
#pragma unroll
        for (int j = 0; j < 8; ++j)
#pragma unroll
            for (int v = 0; v < 4; ++v) acc[i][j][v] = 0.f;

    auto issue_load = [&](int s) {
        const uint32_t st = (uint32_t)(s % 3) * SSTG;
        const int k0 = s << 5;
        const __nv_bfloat16* Asrc = isHi ? Ah : Al;
        const __nv_bfloat16* Bsrc = isHi ? Bh : Bl;
#pragma unroll
        for (int rr = 0; rr < 128; rr += 32) {
            const uint32_t r = lr + rr;
            CP_ASYNC16(sbase + st + sw_off(r, lc),
                       Asrc + (size_t)(row0 + r) * PE + k0 + koff);
            CP_ASYNC16(sbase + st + A_ST + sw_off(r, lc),
                       Bsrc + (size_t)(col0 + r) * PE + k0 + koff);
        }
    };

    issue_load(0); CP_COMMIT();
    issue_load(1); CP_COMMIT();

#pragma unroll 1
    for (int s = 0; s < NKI; ++s) {
        if (s < NKI - 1) CP_WAIT(1);
        else             CP_WAIT(0);
        __syncthreads();
        if (s + 2 < NKI) { issue_load(s + 2); CP_COMMIT(); }

        const uint32_t aB = sbase + (uint32_t)(s % 3) * SSTG;
        const uint32_t bB = aB + A_ST;
#pragma unroll
        for (int ks = 0; ks < 2; ++ks) {
            uint32_t ah[2][4], al[2][4];
#pragma unroll
            for (int mi = 0; mi < 2; ++mi) {
                uint32_t arow = (uint32_t)(wm * 32 + mi * 16 + (lane & 15));
                uint32_t hchunk = (uint32_t)(ks * 2 + (lane >> 4));
                LDMATRIX_X4(ah[mi][0], ah[mi][1], ah[mi][2], ah[mi][3],
                            aB + sw_off(arow, hchunk));
                LDMATRIX_X4(al[mi][0], al[mi][1], al[mi][2], al[mi][3],
                            aB + sw_off(arow, hchunk + 4));
            }
#pragma unroll
            for (int pi = 0; pi < 4; ++pi) {
                uint32_t brow = (uint32_t)(wn * 64 + pi * 16 +
                                           ((lane >> 4) << 3) + (lane & 7));
                uint32_t hchunk = (uint32_t)(ks * 2 + ((lane >> 3) & 1));
                uint32_t bh0, bh1, bh2, bh3, bl0, bl1, bl2, bl3;
                LDMATRIX_X4(bh0, bh1, bh2, bh3, bB + sw_off(brow, hchunk));
                LDMATRIX_X4(bl0, bl1, bl2, bl3, bB + sw_off(brow, hchunk + 4));
#pragma unroll
                for (int mi = 0; mi < 2; ++mi) {
                    MMA16816(acc[mi][2 * pi],     ah[mi][0], ah[mi][1], ah[mi][2], ah[mi][3], bh0, bh1);
                    MMA16816(acc[mi][2 * pi + 1], ah[mi][0], ah[mi][1], ah[mi][2], ah[mi][3], bh2, bh3);
                }
#pragma unroll
                for (int mi = 0; mi < 2; ++mi) {
                    MMA16816(acc[mi][2 * pi],     ah[mi][0], ah[mi][1], ah[mi][2], ah[mi][3], bl0, bl1);
                    MMA16816(acc[mi][2 * pi + 1], ah[mi][0], ah[mi][1], ah[mi][2], ah[mi][3], bl2, bl3);
                }
#pragma unroll
                for (int mi = 0; mi < 2; ++mi) {
                    MMA16816(acc[mi][2 * pi],     al[mi][0], al[mi][1], al[mi][2], al[mi][3], bh0, bh1);
                    MMA16816(acc[mi][2 * pi + 1], al[mi][0], al[mi][1], al[mi][2], al[mi][3], bh2, bh3);
                }
            }
        }
    }

    // Epilogue
    const int tr  = lane >> 2;
    const int tc2 = (lane & 3) * 2;
#pragma unroll
    for (int mi = 0; mi < 2; ++mi) {
#pragma unroll
        for (int ni = 0; ni < 8; ++ni) {
            int col = col0 + wn * 64 + ni * 8 + tc2;
            float2 bi = *reinterpret_cast<const float2*>(bias + col);
            int r1 = row0 + wm * 32 + mi * 16 + tr;
            float v0 = (acc[mi][ni][0] + bi.x) * scale;
            float v1 = (acc[mi][ni][1] + bi.y) * scale;
            float v2 = (acc[mi][ni][2] + bi.x) * scale;
            float v3 = (acc[mi][ni][3] + bi.y) * scale;
            if (outF) {
                *reinterpret_cast<float2*>(&outF[(size_t)r1 * PE + col]) =
                    make_float2(v0, v1);
                *reinterpret_cast<float2*>(&outF[(size_t)(r1 + 8) * PE + col]) =
                    make_float2(v2, v3);
            } else {
                uint32_t h01, l01, h23, l23;
                split2(v0, v1, h01, l01);
                split2(v2, v3, h23, l23);
                *reinterpret_cast<uint32_t*>(outH + (size_t)r1 * PE + col) = h01;
                *reinterpret_cast<uint32_t*>(outL + (size_t)r1 * PE + col) = l01;
                *reinterpret_cast<uint32_t*>(outH + (size_t)(r1 + 8) * PE + col) = h23;
                *reinterpret_cast<uint32_t*>(outL + (size_t)(r1 + 8) * PE + col) = l23;
            }
        }
    }
}

// Fused Q/K/V projection: blockIdx.z selects weight/bias/output/scale.
__global__ __launch_bounds__(256, 2) void gemm_qkv_kernel(
    const __nv_bfloat16* __restrict__ xh, const __nv_bfloat16* __restrict__ xl,
    const __nv_bfloat16* __restrict__ Wth, const __nv_bfloat16* __restrict__ Wtl,
    const float* __restrict__ bq, const float* __restrict__ bk,
    const float* __restrict__ bv,
    __nv_bfloat16* __restrict__ Qh, __nv_bfloat16* __restrict__ Ql,
    __nv_bfloat16* __restrict__ Kh, __nv_bfloat16* __restrict__ Kl,
    __nv_bfloat16* __restrict__ Vh, __nv_bfloat16* __restrict__ Vl)
{
    extern __shared__ char smem[];
    const int z = blockIdx.z;
    const size_t WSZ = (size_t)PE * PE;
    const float* bias = (z == 0) ? bq : (z == 1) ? bk : bv;
    __nv_bfloat16* oh = (z == 0) ? Qh : (z == 1) ? Kh : Vh;
    __nv_bfloat16* ol = (z == 0) ? Ql : (z == 1) ? Kl : Vl;
    const float scale = (z == 0) ? QSCALE : 1.f;
    gemm_body(xh, xl, Wth + z * WSZ, Wtl + z * WSZ, bias, scale,
              nullptr, oh, ol, smem);
}

// O-projection (fp32 output)
__global__ __launch_bounds__(256, 2) void gemm_o_kernel(
    const __nv_bfloat16* __restrict__ aoh, const __nv_bfloat16* __restrict__ aol,
    const __nv_bfloat16* __restrict__ Bh, const __nv_bfloat16* __restrict__ Bl,
    const float* __restrict__ bias, float* __restrict__ outF)
{
    extern __shared__ char smem[];
    gemm_body(aoh, aol, Bh, Bl, bias, 1.f, outF, nullptr, nullptr, smem);
}

// ---------------------------------------------------------------------------
// fp32 -> (hi, lo) bf16 split (x only), 4 elems/thread vectorized
// ---------------------------------------------------------------------------
__global__ __launch_bounds__(256) void split_kernel(
    const float* __restrict__ in, __nv_bfloat16* __restrict__ hi,
    __nv_bfloat16* __restrict__ lo, int n4)
{
    int i = blockIdx.x * 256 + threadIdx.x;
    if (i < n4) {
        float4 v = reinterpret_cast<const float4*>(in)[i];
        uint32_t h01, l01, h23, l23;
        split2(v.x, v.y, h01, l01);
        split2(v.z, v.w, h23, l23);
        reinterpret_cast<uint2*>(hi)[i] = make_uint2(h01, h23);
        reinterpret_cast<uint2*>(lo)[i] = make_uint2(l01, l23);
    }
}

// W[k][n] fp32 -> Wt[n][k] bf16 hi/lo; z selects which of 4 weights
__global__ __launch_bounds__(256) void transpose_split_kernel(
    const float* __restrict__ W0, const float* __restrict__ W1,
    const float* __restrict__ W2, const float* __restrict__ W3,
    __nv_bfloat16* __restrict__ Th, __nv_bfloat16* __restrict__ Tl)
{
    __shared__ float t[32][33];
    const int z = blockIdx.z;
    const float* W = (z == 0) ? W0 : (z == 1) ? W1 : (z == 2) ? W2 : W3;
    const size_t WSZ = (size_t)PE * PE;
    __nv_bfloat16* Thz = Th + z * WSZ;
    __nv_bfloat16* Tlz = Tl + z * WSZ;
    const int n0 = blockIdx.x * 32;
    const int k0 = blockIdx.y * 32;
    const int tx = threadIdx.x & 31;
    const int ty = threadIdx.x >> 5;
#pragma unroll
    for (int i = 0; i < 32; i += 8)
        t[ty + i][tx] = W[(size_t)(k0 + ty + i) * PE + n0 + tx];
    __syncthreads();
#pragma unroll
    for (int i = 0; i < 32; i += 8) {
        float v = t[tx][ty + i];
        __nv_bfloat16 h = __float2bfloat16(v);
        size_t idx = (size_t)(n0 + ty + i) * PE + k0 + tx;
        Thz[idx] = h;
        Tlz[idx] = __float2bfloat16(v - __bfloat162float(h));
    }
}

// ---------------------------------------------------------------------------
// Flash attention with mma.sync bf16 + hi/lo splitting.
// NO __syncthreads in the mainloop: 2-slot mbarrier pipeline
//   full[slot]:  128 x cp.async.mbarrier.arrive.noinc (load completion)
//   empty[slot]: 128 x mbarrier.arrive (after PV reads)
// Warps skew up to one tile -> tensor/softmax phases interleave across warps.
// ---------------------------------------------------------------------------
#define LDT 72                  // smem row stride in bf16 (144 B)
#define TSZ (64 * LDT)
#define STILE(buf, arr) (((buf) * 4 + (arr)) * TSZ)
#define MBAR_OFF (8 * TSZ * 2)           // 73728: full[0],full[1],empty[0],empty[1]
#define ATTN_SMEM_BYTES (MBAR_OFF + 64)  // 73792

__global__ __launch_bounds__(128, 3) void attn_mma_kernel(
    const __nv_bfloat16* __restrict__ Qh_g, const __nv_bfloat16* __restrict__ Ql_g,
    const __nv_bfloat16* __restrict__ Kh_g, const __nv_bfloat16* __restrict__ Kl_g,
    const __nv_bfloat16* __restrict__ Vh_g, const __nv_bfloat16* __restrict__ Vl_g,
    __nv_bfloat16* __restrict__ AOh, __nv_bfloat16* __restrict__ AOl)
{
    extern __shared__ __nv_bfloat16 smemb[];
    const uint32_t sb = smem_u32(smemb);
    const uint32_t mb_full  = sb + MBAR_OFF;        // +0, +8
    const uint32_t mb_empty = sb + MBAR_OFF + 16;   // +0, +8

    const int tid  = threadIdx.x;
    const int lane = tid & 31;
    const int wm   = tid >> 5;
    const int qb   = gridDim.x - 1 - blockIdx.x;
    const int q0   = qb * 64;
    const int bh   = blockIdx.y;
    const int b    = bh >> 4;
    const int h    = bh & 15;
    const size_t base = (size_t)b * PS * PE + (size_t)h * PD;

    if (tid == 0) {
        MBAR_INIT(mb_full,      128u);
        MBAR_INIT(mb_full + 8,  128u);
        MBAR_INIT(mb_empty,     128u);
        MBAR_INIT(mb_empty + 8, 128u);
    }

    auto ld_tile = [&](const __nv_bfloat16* g, uint32_t soff, int row0g) {
#pragma unroll
        for (int it = 0; it < 4; ++it) {
            int i = tid + it * 128;
            int r = i >> 3, c = i & 7;
            uint32_t dst = sb + (soff + r * LDT + c * 8) * 2;
            const void* src = g + base + (size_t)(row0g + r) * PE + c * 8;
            CP_ASYNC16(dst, src);
        }
    };
    auto ld_kv = [&](int slot, int kv0) {
        ld_tile(Kh_g, STILE(slot, 0), kv0);
        ld_tile(Kl_g, STILE(slot, 1), kv0);
        ld_tile(Vh_g, STILE(slot, 2), kv0);
        ld_tile(Vl_g, STILE(slot, 3), kv0);
        CP_MBAR_ARRIVE(mb_full + (uint32_t)slot * 8u);
    };

    // ---- Q staging (overlaid on ring slot0) ----
    ld_tile(Qh_g, STILE(0, 0), q0);
    ld_tile(Ql_g, STILE(0, 1), q0);
    CP_COMMIT();
    CP_WAIT(0);
    __syncthreads();   // also publishes mbarrier init

    uint32_t qfh[4][4], qfl[4][4];
    {
        uint32_t qoff = ((uint32_t)(wm * 16 + (lane & 15)) * LDT + (lane >> 4) * 8) * 2;
#pragma unroll
        for (int ks = 0; ks < 4; ++ks) {
            LDMATRIX_X4(qfh[ks][0], qfh[ks][1], qfh[ks][2], qfh[ks][3],
                        sb + (STILE(0, 0) * 2) + qoff + ks * 32);
            LDMATRIX_X4(qfl[ks][0], qfl[ks][1], qfl[ks][2], qfl[ks][3],
                        sb + (STILE(0, 1) * 2) + qoff + ks * 32);
        }
    }
    __syncthreads();   // all warps done reading Q before KV overwrites slot0

    // ---- KV tile 0 into slot0 (per-thread async, completion via mbarrier) ----
    ld_kv(0, 0);

    float O[8][4];
#pragma unroll
    for (int g = 0; g < 8; ++g)
#pragma unroll
        for (int j = 0; j < 4; ++j) O[g][j] = 0.f;
    float m0 = -1e30f, m1 = -1e30f, sl0 = 0.f, sl1 = 0.f;

    const uint32_t klo = ((((lane >> 4) << 3) + (lane & 7)) * LDT + ((lane >> 3) & 1) * 8) * 2;
    const uint32_t vlo = ((lane & 15) * LDT + (lane >> 4) * 8) * 2;
    const int ntiles = qb + 1;

#pragma unroll 1
    for (int t = 0; t < ntiles; ++t) {
        const int slot = t & 1;

        // producer step: load tile t+1 (backpressure via empty[slot'])
        if (t + 1 < ntiles) {
            const int tp = t + 1;
            const int ps = tp & 1;
            if (tp >= 2)
                MBAR_WAIT_PARITY(mb_empty + (uint32_t)ps * 8u, ((tp - 2) >> 1) & 1);
            ld_kv(ps, tp * 64);
        }

        // consumer: wait for tile t data
        MBAR_WAIT_PARITY(mb_full + (uint32_t)slot * 8u, (t >> 1) & 1);

        const uint32_t kHb = sb + STILE(slot, 0) * 2;
        const uint32_t kLb = sb + STILE(slot, 1) * 2;
        const uint32_t vHb = sb + STILE(slot, 2) * 2;
        const uint32_t vLb = sb + STILE(slot, 3) * 2;

        float S[8][4];
#pragma unroll
        for (int g = 0; g < 8; ++g)
#pragma unroll
            for (int j = 0; j < 4; ++j) S[g][j] = 0.f;

        // ---- S = QK^T (R7 interleaved ordering) ----
#pragma unroll
        for (int ks = 0; ks < 4; ++ks) {
#pragma unroll
            for (int ni = 0; ni < 4; ++ni) {
                uint32_t off = klo + (uint32_t)(ni * 16 * LDT + ks * 16) * 2;
                uint32_t bh0, bh1, bh2, bh3, bl0, bl1, bl2, bl3;
                LDMATRIX_X4(bh0, bh1, bh2, bh3, kHb + off);
                LDMATRIX_X4(bl0, bl1, bl2, bl3, kLb + off);
                MMA16816(S[2 * ni],     qfh[ks][0], qfh[ks][1], qfh[ks][2], qfh[ks][3], bh0, bh1);
                MMA16816(S[2 * ni + 1], qfh[ks][0], qfh[ks][1], qfh[ks][2], qfh[ks][3], bh2, bh3);
                MMA16816(S[2 * ni],     qfh[ks][0], qfh[ks][1], qfh[ks][2], qfh[ks][3], bl0, bl1);
                MMA16816(S[2 * ni + 1], qfh[ks][0], qfh[ks][1], qfh[ks][2], qfh[ks][3], bl2, bl3);
                MMA16816(S[2 * ni],     qfl[ks][0], qfl[ks][1], qfl[ks][2], qfl[ks][3], bh0, bh1);
                MMA16816(S[2 * ni + 1], qfl[ks][0], qfl[ks][1], qfl[ks][2], qfl[ks][3], bh2, bh3);
            }
        }

        if (t == ntiles - 1) {
            const int kv0 = t * 64;
            const int row0g = q0 + wm * 16 + (lane >> 2);
#pragma unroll
            for (int g = 0; g < 8; ++g) {
                int colg = kv0 + 8 * g + ((lane & 3) << 1);
                if (colg > row0g)         S[g][0] = -1e30f;
                if (colg + 1 > row0g)     S[g][1] = -1e30f;
                if (colg > row0g + 8)     S[g][2] = -1e30f;
                if (colg + 1 > row0g + 8) S[g][3] = -1e30f;
            }
        }

        float mt0 = -1e30f, mt1 = -1e30f;
#pragma unroll
        for (int g = 0; g < 8; ++g) {
            mt0 = fmaxf(mt0, fmaxf(S[g][0], S[g][1]));
            mt1 = fmaxf(mt1, fmaxf(S[g][2], S[g][3]));
        }
        mt0 = fmaxf(mt0, __shfl_xor_sync(0xffffffffu, mt0, 1));
        mt0 = fmaxf(mt0, __shfl_xor_sync(0xffffffffu, mt0, 2));
        mt1 = fmaxf(mt1, __shfl_xor_sync(0xffffffffu, mt1, 1));
        mt1 = fmaxf(mt1, __shfl_xor_sync(0xffffffffu, mt1, 2));
        float mn0 = fmaxf(m0, mt0), mn1 = fmaxf(m1, mt1);
        float c0 = ex2(m0 - mn0), c1 = ex2(m1 - mn1);
        m0 = mn0; m1 = mn1;
        float rs0 = 0.f, rs1 = 0.f;
#pragma unroll
        for (int g = 0; g < 8; ++g) {
            S[g][0] = ex2(S[g][0] - mn0); rs0 += S[g][0];
            S[g][1] = ex2(S[g][1] - mn0); rs0 += S[g][1];
            S[g][2] = ex2(S[g][2] - mn1); rs1 += S[g][2];
            S[g][3] = ex2(S[g][3] - mn1); rs1 += S[g][3];
        }
        rs0 += __shfl_xor_sync(0xffffffffu, rs0, 1);
        rs0 += __shfl_xor_sync(0xffffffffu, rs0, 2);
        rs1 += __shfl_xor_sync(0xffffffffu, rs1, 1);
        rs1 += __shfl_xor_sync(0xffffffffu, rs1, 2);
        sl0 = sl0 * c0 + rs0;
        sl1 = sl1 * c1 + rs1;
#pragma unroll
        for (int g = 0; g < 8; ++g) {
            O[g][0] *= c0; O[g][1] *= c0;
            O[g][2] *= c1; O[g][3] *= c1;
        }

        // ---- O += P V (R7 interleaved ordering) ----
#pragma unroll
        for (int ks = 0; ks < 4; ++ks) {
            uint32_t pha[4], pla[4];
            split2(S[2 * ks][0],     S[2 * ks][1],     pha[0], pla[0]);
            split2(S[2 * ks][2],     S[2 * ks][3],     pha[1], pla[1]);
            split2(S[2 * ks + 1][0], S[2 * ks + 1][1], pha[2], pla[2]);
            split2(S[2 * ks + 1][2], S[2 * ks + 1][3], pha[3], pla[3]);
#pragma unroll
            for (int ni = 0; ni < 4; ++ni) {
                uint32_t off = vlo + (uint32_t)(ks * 16 * LDT + ni * 16) * 2;
                uint32_t vh0, vh1, vh2, vh3, vl0_, vl1_, vl2_, vl3_;
                LDMATRIX_X4_T(vh0, vh1, vh2, vh3, vHb + off);
                LDMATRIX_X4_T(vl0_, vl1_, vl2_, vl3_, vLb + off);
                MMA16816(O[2 * ni],     pha[0], pha[1], pha[2], pha[3], vh0, vh1);
                MMA16816(O[2 * ni + 1], pha[0], pha[1], pha[2], pha[3], vh2, vh3);
                MMA16816(O[2 * ni],     pha[0], pha[1], pha[2], pha[3], vl0_, vl1_);
                MMA16816(O[2 * ni + 1], pha[0], pha[1], pha[2], pha[3], vl2_, vl3_);
                MMA16816(O[2 * ni],     pla[0], pla[1], pla[2], pla[3], vh0, vh1);
                MMA16816(O[2 * ni + 1], pla[0], pla[1], pla[2], pla[3], vh2, vh3);
            }
        }

        // this thread is done reading slot t
        MBAR_ARRIVE(mb_empty + (uint32_t)slot * 8u);
    }

    const float inv0 = 1.f / sl0;
    const float inv1 = 1.f / sl1;
    const int r0g = q0 + wm * 16 + (lane >> 2);
#pragma unroll
    for (int g = 0; g < 8; ++g) {
        int colg = 8 * g + ((lane & 3) << 1);
        size_t i0 = base + (size_t)r0g * PE + colg;
        size_t i1 = base + (size_t)(r0g + 8) * PE + colg;
        uint32_t h01, l01, h23, l23;
        split2(O[g][0] * inv0, O[g][1] * inv0, h01, l01);
        split2(O[g][2] * inv1, O[g][3] * inv1, h23, l23);
        *reinterpret_cast<uint32_t*>(AOh + i0) = h01;
        *reinterpret_cast<uint32_t*>(AOl + i0) = l01;
        *reinterpret_cast<uint32_t*>(AOh + i1) = h23;
        *reinterpret_cast<uint32_t*>(AOl + i1) = l23;
    }
}

// ---------------------------------------------------------------------------
extern "C" void kernel_launch(void* const* d_in, const int* in_sizes, int n_in,
                              void* d_out, int out_size)
{
    const float* x  = (const float*)d_in[0];
    const float* Wq = (const float*)d_in[1];
    const float* bq = (const float*)d_in[2];
    const float* Wk = (const float*)d_in[3];
    const float* bk = (const float*)d_in[4];
    const float* Wv = (const float*)d_in[5];
    const float* bv = (const float*)d_in[6];
    const float* Wo = (const float*)d_in[7];
    const float* bo = (const float*)d_in[8];
    float* out = (float*)d_out;

    __nv_bfloat16 *xh, *xl, *Qh, *Ql, *Kh, *Kl, *Vh, *Vl, *aoh, *aol, *Wth, *Wtl;
    cudaGetSymbolAddress((void**)&xh,  g_xh);
    cudaGetSymbolAddress((void**)&xl,  g_xl);
    cudaGetSymbolAddress((void**)&Qh,  g_Qh);
    cudaGetSymbolAddress((void**)&Ql,  g_Ql);
    cudaGetSymbolAddress((void**)&Kh,  g_Kh);
    cudaGetSymbolAddress((void**)&Kl,  g_Kl);
    cudaGetSymbolAddress((void**)&Vh,  g_Vh);
    cudaGetSymbolAddress((void**)&Vl,  g_Vl);
    cudaGetSymbolAddress((void**)&aoh, g_aoh);
    cudaGetSymbolAddress((void**)&aol, g_aol);
    cudaGetSymbolAddress((void**)&Wth, g_Wth);
    cudaGetSymbolAddress((void**)&Wtl, g_Wtl);

    cudaFuncSetAttribute(attn_mma_kernel,
                         cudaFuncAttributeMaxDynamicSharedMemorySize,
                         ATTN_SMEM_BYTES);
    cudaFuncSetAttribute(gemm_qkv_kernel,
                         cudaFuncAttributeMaxDynamicSharedMemorySize,
                         GEMM_SMEM_BYTES);
    cudaFuncSetAttribute(gemm_o_kernel,
                         cudaFuncAttributeMaxDynamicSharedMemorySize,
                         GEMM_SMEM_BYTES);

    const size_t WSZ = (size_t)PE * PE;
    const int nX4 = PBS * PE / 4;

    split_kernel<<<(nX4 + 255) / 256, 256>>>(x, xh, xl, nX4);
    transpose_split_kernel<<<dim3(PE / 32, PE / 32, 4), 256>>>(
        Wq, Wk, Wv, Wo, Wth, Wtl);

    gemm_qkv_kernel<<<dim3(PE / GBN, PBS / GBM, 3), 256, GEMM_SMEM_BYTES>>>(
        xh, xl, Wth, Wtl, bq, bk, bv, Qh, Ql, Kh, Kl, Vh, Vl);

    attn_mma_kernel<<<dim3(PS / 64, PB * PH), 128, ATTN_SMEM_BYTES>>>(
        Qh, Ql, Kh, Kl, Vh, Vl, aoh, aol);

    gemm_o_kernel<<<dim3(PE / GBN, PBS / GBM), 256, GEMM_SMEM_BYTES>>>(
        aoh, aol, Wth + 3 * WSZ, Wtl + 3 * WSZ, bo, out);
}